// round 9
// baseline (speedup 1.0000x reference)
#include <cuda_runtime.h>

#define NB   32
#define NA   8400
#define ROWF 85
#define MD   300
#define TOTAL (NB*NA)
#define CONF_T 0.2f
#define NMS_T  0.45f
#define RS   92          // padded smem row stride (words): 16B-aligned, conflict-free LDS.128

// output layout: concatenated float32, reference return order
#define OF_BOX  0         // 32*300*4 = 38400
#define OF_INZ  38400     // 9600
#define OF_SC   48000     // 9600
#define OF_CLS  57600     // 9600
#define OF_CTR  67200     // 19200
#define OF_KEEP 86400     // 9600  -> total 96000

__device__ unsigned g_keys[TOTAL];      // ordered score bits (0 if below thresh)
__device__ float4   g_sbox[NB*MD];
__device__ float    g_sarea[NB*MD];
__device__ unsigned g_flags[NB*20];     // [0..9] valid, [10..19] inside
__device__ unsigned g_mask[NB*10*320];  // TRANSPOSED: [b][chunk][row]

// ---------------------------------------------------------------------------
// Kernel A: per-anchor score -> 32-bit key.
// Stage into stride-92 padded smem; tail = 10 x LDS.128 per half-anchor.
// ---------------------------------------------------------------------------
__global__ void __launch_bounds__(256) score_kernel(const float* __restrict__ pred)
{
    __shared__ float sm[128 * RS];
    __shared__ float red[256];

    const float4* src = reinterpret_cast<const float4*>(pred) +
                        (size_t)blockIdx.x * (128 * ROWF / 4);
#pragma unroll
    for (int i = threadIdx.x; i < 128 * ROWF / 4; i += 256) {
        float4 v = src[i];
        int f = 4 * i;
        int r = f / 85;
        int c = f - r * 85;
        sm[r*RS + c] = v.x;
        if (++c == 85) { c = 0; ++r; }  sm[r*RS + c] = v.y;
        if (++c == 85) { c = 0; ++r; }  sm[r*RS + c] = v.z;
        if (++c == 85) { c = 0; ++r; }  sm[r*RS + c] = v.w;
    }
    __syncthreads();

    const int anchor = threadIdx.x & 127;
    const int half   = threadIdx.x >> 7;         // warp-uniform
    const float4* av = reinterpret_cast<const float4*>(sm + anchor * RS);

    float m0, m1;
    if (half == 0) {     // classes 5,6,7 + vectors j=2,4,...,18 (words 12..79)
        float4 v = av[1];                         // words 4..7: obj,c0,c1,c2
        m0 = fmaxf(v.y, v.z); m1 = v.w;
#pragma unroll
        for (int j = 2; j < 20; j += 2) {
            v = av[1 + j];
            m0 = fmaxf(m0, fmaxf(v.x, v.y));
            m1 = fmaxf(m1, fmaxf(v.z, v.w));
        }
    } else {             // vectors j=1,3,...,19 (words 8..83) + word 84
        float4 v = av[2];
        m0 = fmaxf(v.x, v.y); m1 = fmaxf(v.z, v.w);
#pragma unroll
        for (int j = 3; j < 20; j += 2) {
            v = av[1 + j];
            m0 = fmaxf(m0, fmaxf(v.x, v.y));
            m1 = fmaxf(m1, fmaxf(v.z, v.w));
        }
        m1 = fmaxf(m1, sm[anchor*RS + 84]);
    }
    red[threadIdx.x] = fmaxf(m0, m1);
    __syncthreads();

    if (threadIdx.x < 128) {
        float conf  = fmaxf(red[threadIdx.x], red[threadIdx.x + 128]);
        float obj   = sm[anchor*RS + 4];
        float score = __fmul_rn(obj, conf);
        unsigned key = 0u;
        if (score >= CONF_T) key = __float_as_uint(score) | 0x80000000u;
        g_keys[blockIdx.x * 128 + anchor] = key;
    }
}

// ---------------------------------------------------------------------------
// Kernel B: per-batch select+sort+decode (32 blocks x 1024). Unchanged.
// ---------------------------------------------------------------------------
struct SelSmem {
    unsigned shi[NA];
    unsigned hist[4096];
    unsigned s8[512];
    unsigned sgsuf[33];
    unsigned long long cand[512];
    unsigned sh_bin, sh_acc, ncand;
    unsigned validw[10], inw[10];
};
#define SEL_SMEM_BYTES ((int)sizeof(SelSmem))

__global__ void __launch_bounds__(1024, 1) select_kernel(const float* __restrict__ pred,
                                                         const float* __restrict__ zone,
                                                         float* __restrict__ out)
{
    extern __shared__ char smem_raw[];
    SelSmem& S = *reinterpret_cast<SelSmem*>(smem_raw);

    const int b   = blockIdx.x;
    const int tid = threadIdx.x;

    if (tid == 0) { S.sh_bin = 0u; S.sh_acc = 0u; S.ncand = 0u; }
    if (tid < 10) { S.validw[tid] = 0u; S.inw[tid] = 0u; }
    for (int i = tid; i < 4096; i += 1024) S.hist[i] = 0u;
    __syncthreads();

    {
        const unsigned* __restrict__ keys = g_keys + (size_t)b * NA;
        for (int i = tid; i < NA; i += 1024) {
            unsigned hi = keys[i];
            S.shi[i] = hi;
            unsigned d = hi >> 20;
            unsigned am = __activemask();
            unsigned mm = __match_any_sync(am, d);
            if ((tid & 31) == (int)(__ffs(mm) - 1u))
                atomicAdd(&S.hist[d], (unsigned)__popc(mm));
        }
    }
    __syncthreads();

    unsigned thresh24 = 0u;

#pragma unroll
    for (int pass = 0; pass < 2; ++pass) {
        if (tid < 512) {
            unsigned s = 0;
#pragma unroll
            for (int k = 0; k < 8; ++k) s += S.hist[tid * 8 + k];
            S.s8[tid] = s;
        }
        __syncthreads();
        if (tid < 32) {
            unsigned s = 0;
#pragma unroll
            for (int k = 0; k < 16; ++k) s += S.s8[tid * 16 + k];
#pragma unroll
            for (int off = 1; off < 32; off <<= 1) {
                unsigned v = __shfl_down_sync(0xffffffffu, s, off);
                if (tid + off < 32) s += v;
            }
            S.sgsuf[tid] = s;
            if (tid == 0) S.sgsuf[32] = 0u;
        }
        __syncthreads();
        unsigned need = (unsigned)MD - S.sh_acc;
        if (tid < 512) {
            int g = tid >> 4;
            unsigned ws = 0;
            for (int j = tid + 1; j < (g + 1) * 16; ++j) ws += S.s8[j];
            unsigned above = S.sgsuf[g + 1] + ws;
            unsigned here  = above + S.s8[tid];
            if (here >= need && above < need) {
                unsigned cum = above; int sel = 0;
#pragma unroll
                for (int k = 7; k >= 0; --k) {
                    unsigned c = S.hist[tid * 8 + k];
                    if (cum + c >= need) { sel = k; break; }
                    cum += c;
                }
                S.sh_bin = (unsigned)(tid * 8 + sel);
                S.sh_acc += cum;
            }
        }
        __syncthreads();

        if (pass == 0) {
            unsigned p0 = S.sh_bin;
            __syncthreads();
            for (int i = tid; i < 4096; i += 1024) S.hist[i] = 0u;
            __syncthreads();
            for (int i = tid; i < NA; i += 1024) {
                unsigned hi = S.shi[i];
                if ((hi >> 20) == p0) {
                    unsigned d = (hi >> 8) & 0xFFFu;
                    unsigned am = __activemask();
                    unsigned mm = __match_any_sync(am, d);
                    if ((tid & 31) == (int)(__ffs(mm) - 1u))
                        atomicAdd(&S.hist[d], (unsigned)__popc(mm));
                }
            }
            __syncthreads();
            thresh24 = p0 << 12;
        } else {
            thresh24 |= S.sh_bin;
        }
    }

    for (int i = tid; i < NA; i += 1024) {
        unsigned hi = S.shi[i];
        if ((hi >> 8) >= thresh24) {
            unsigned p = atomicAdd(&S.ncand, 1u);
            if (p < 512u)
                S.cand[p] = ((unsigned long long)hi << 32) | (unsigned)(~(unsigned)i);
        }
    }
    __syncthreads();
    {
        unsigned nc = S.ncand; if (nc > 512u) nc = 512u;
        if (tid < 512 && (unsigned)tid >= nc) S.cand[tid] = 0ull;
    }
    __syncthreads();

    unsigned long long v = (tid < 512) ? S.cand[tid] : 0ull;
    for (int size = 2; size <= 512; size <<= 1) {
        for (int stride = size >> 1; stride > 0; stride >>= 1) {
            if (stride >= 32) {
                __syncthreads();
                if (tid < 512) S.cand[tid] = v;
                __syncthreads();
                if (tid < 512) {
                    unsigned long long vp = S.cand[tid ^ stride];
                    bool takeMax = ((tid & stride) == 0) == ((tid & size) == 0);
                    v = takeMax ? (v > vp ? v : vp) : (v < vp ? v : vp);
                }
            } else if (tid < 512) {
                unsigned long long vp = __shfl_xor_sync(0xffffffffu, v, stride);
                bool takeMax = ((tid & stride) == 0) == ((tid & size) == 0);
                v = takeMax ? (v > vp ? v : vp) : (v < vp ? v : vp);
            }
        }
    }

    if (tid < MD) {
        unsigned long long kk = v;
        unsigned aidx = ~((unsigned)kk);
        bool valid = (kk >> 32) != 0ull;
        if (!valid) aidx = 0;
        const float* a = pred + (size_t)(b * NA + aidx) * ROWF;

        float x = a[0], y = a[1], w = a[2], h = a[3], obj = a[4];

        float conf = a[5]; int cls = 0;
#pragma unroll 8
        for (int k = 1; k < 80; ++k) {
            float c = a[5 + k];
            if (c > conf) { conf = c; cls = k; }       // first-max == jnp.argmax
        }

        float hw = __fmul_rn(w, 0.5f), hh = __fmul_rn(h, 0.5f);
        float4 v0 = make_float4(__fadd_rn(x,-hw), __fadd_rn(y,-hh),
                                __fadd_rn(x, hw), __fadd_rn(y, hh));

        g_sbox[b*MD + tid]  = v0;
        g_sarea[b*MD + tid] = __fmul_rn(fmaxf(__fadd_rn(v0.z, -v0.x), 0.f),
                                        fmaxf(__fadd_rn(v0.w, -v0.y), 0.f));
        if (valid) atomicOr(&S.validw[tid >> 5], 1u << (tid & 31));

        float cx = __fmul_rn(__fadd_rn(v0.x, v0.z), 0.5f);
        float cy = __fmul_rn(__fadd_rn(v0.y, v0.w), 0.5f);

        int cnt = 0;
#pragma unroll
        for (int k2 = 0; k2 < 8; ++k2) {
            int km = (k2 + 7) & 7;
            float xi = zone[2*k2], yi = zone[2*k2+1];
            float xj = zone[2*km], yj = zone[2*km+1];
            bool gyi = yi > cy, gyj = yj > cy;
            if (gyi != gyj) {
                float gx = __fadd_rn(
                    __fdiv_rn(__fmul_rn(__fadd_rn(xj,-xi), __fadd_rn(cy,-yi)),
                              __fadd_rn(yj,-yi)), xi);
                if (gx > cx) cnt++;
            }
        }
        if (cnt & 1) atomicOr(&S.inw[tid >> 5], 1u << (tid & 31));

        size_t o = (size_t)b * MD + tid;
        out[OF_BOX + o*4 + 0] = v0.y;  out[OF_BOX + o*4 + 1] = v0.x;
        out[OF_BOX + o*4 + 2] = v0.w;  out[OF_BOX + o*4 + 3] = v0.z;
        out[OF_SC  + o]       = fmaxf(obj, conf);
        out[OF_CLS + o]       = (float)cls;
        out[OF_CTR + o*2]     = cy;    out[OF_CTR + o*2 + 1] = cx;
    }
    __syncthreads();
    if (tid < 10) {
        g_flags[b*20 + tid]      = S.validw[tid];
        g_flags[b*20 + 10 + tid] = S.inw[tid];
    }
}

// ---------------------------------------------------------------------------
// Kernel C: suppression bitmask (320 blocks x 640), TRANSPOSED write.
// ---------------------------------------------------------------------------
__global__ void __launch_bounds__(640) mask_kernel()
{
    __shared__ float4 sbb[MD];
    __shared__ float  sA[MD];

    const int b  = blockIdx.x / 10;
    const int rg = blockIdx.x % 10;
    const int tid = threadIdx.x;

    if (tid < MD) { sbb[tid] = g_sbox[b*MD + tid]; sA[tid] = g_sarea[b*MD + tid]; }
    __syncthreads();

    int w = tid >> 5, l = tid & 31;
    int c    = w % 10;
    int half = w / 10;
    int i0   = rg * 30 + half * 15;
    int j    = c * 32 + l;
    int jmax = c * 32 + 31;
    bool jv  = (j < MD);
    float4 bj = jv ? sbb[j] : make_float4(0,0,0,0);
    float  ja = jv ? sA[j] : 0.f;

    for (int i = i0; i < i0 + 15; ++i) {
        unsigned bits = 0u;
        if (jmax > i) {
            float4 bi = sbb[i];
            float  ia = sA[i];
            bool sup = false;
            if (jv && j > i) {
                float ltx = fmaxf(bi.x, bj.x), lty = fmaxf(bi.y, bj.y);
                float rbx = fminf(bi.z, bj.z), rby = fminf(bi.w, bj.w);
                float iw  = fmaxf(__fadd_rn(rbx, -ltx), 0.f);
                float ih  = fmaxf(__fadd_rn(rby, -lty), 0.f);
                float inter = __fmul_rn(iw, ih);
                float denom = __fadd_rn(__fadd_rn(__fadd_rn(ia, ja), -inter), 1e-9f);
                sup = inter > __fmul_rn(NMS_T, denom);
            }
            bits = __ballot_sync(0xffffffffu, sup);
        }
        if (l == 0) g_mask[(b*10 + c)*320 + i] = bits;
    }
}

// ---------------------------------------------------------------------------
// Kernel D: ffs-skip greedy scan — iterates ONLY over kept boxes.
// smem mask transposed [chunk][row] with stride 321 (conflict-free).
// ---------------------------------------------------------------------------
__global__ void __launch_bounds__(512, 1) fin_kernel(float* __restrict__ out)
{
    __shared__ unsigned smaskT[10*321];
    __shared__ unsigned keepw[10];
    __shared__ unsigned flg[20];

    const int b   = blockIdx.x;
    const int tid = threadIdx.x;

    for (int idx = tid; idx < 3000; idx += 512) {
        int c = idx / 300, i = idx - c * 300;
        smaskT[c*321 + i] = g_mask[(b*10 + c)*320 + i];
    }
    if (tid < 20) flg[tid] = g_flags[b*20 + tid];
    __syncthreads();

    if (tid < 32) {
        const int l  = tid;
        const int lw = (l < 10) ? l : 0;
        unsigned kw = (l < 10) ? flg[l] : 0u;

        for (int blk = 0; blk < 10; ++blk) {
            unsigned todo = __shfl_sync(0xffffffffu, kw, blk);   // surviving rows
            const int base = blk * 32;
            while (todo) {
                int k = __ffs(todo) - 1;                          // warp-uniform
                unsigned diag = smaskT[blk*321 + base + k];       // broadcast LDS
                unsigned mine = smaskT[lw *321 + base + k];       // per-lane LDS
                kw   &= ~mine;                                    // apply row's mask
                todo &= ~(1u << k);
                todo &= ~diag;                                    // skip suppressed
            }
        }
        if (l < 10) keepw[l] = kw;
    }
    __syncthreads();

    if (tid < MD) {
        unsigned kp = (keepw[tid >> 5] >> (tid & 31)) & 1u;
        unsigned in = (flg[10 + (tid >> 5)] >> (tid & 31)) & 1u;
        size_t o = (size_t)b * MD + tid;
        out[OF_KEEP + o] = (float)kp;
        out[OF_INZ  + o] = (kp && in) ? 1.f : 0.f;
    }
}

extern "C" void kernel_launch(void* const* d_in, const int* in_sizes, int n_in,
                              void* d_out, int out_size)
{
    const float* pred = (const float*)d_in[0];
    const float* zone = (const float*)d_in[1];
    float* out = (float*)d_out;

    static int attr_done = 0;
    if (!attr_done) {
        cudaFuncSetAttribute(select_kernel,
                             cudaFuncAttributeMaxDynamicSharedMemorySize,
                             SEL_SMEM_BYTES);
        attr_done = 1;
    }

    score_kernel<<<TOTAL / 128, 256>>>(pred);
    select_kernel<<<NB, 1024, SEL_SMEM_BYTES>>>(pred, zone, out);
    mask_kernel<<<NB * 10, 640>>>();
    fin_kernel<<<NB, 512>>>(out);
}

// round 10
// speedup vs baseline: 1.1337x; 1.1337x over previous
#include <cuda_runtime.h>

#define NB   32
#define NA   8400
#define ROWF 85
#define MD   300
#define TOTAL (NB*NA)
#define CONF_T 0.2f
#define NMS_T  0.45f

// output layout: concatenated float32, reference return order
#define OF_BOX  0         // 32*300*4 = 38400
#define OF_INZ  38400     // 9600
#define OF_SC   48000     // 9600
#define OF_CLS  57600     // 9600
#define OF_CTR  67200     // 19200
#define OF_KEEP 86400     // 9600  -> total 96000

__device__ unsigned g_keys[TOTAL];     // ordered score bits (0 if below thresh)
__device__ float4   g_sbox[NB*MD];
__device__ float    g_sarea[NB*MD];
__device__ unsigned g_flags[NB*20];    // [0..9] valid, [10..19] inside
__device__ unsigned g_mask[NB*MD*10];  // row-major [b][row][chunk]

// ---------------------------------------------------------------------------
// Kernel A: per-anchor score -> 32-bit key.
// Staging: 11 predicated LDG.128 batched into registers (explicit MLP),
// then stores. Tail: lane-pair class-max split.
// ---------------------------------------------------------------------------
__global__ void __launch_bounds__(256) score_kernel(const float* __restrict__ pred)
{
    __shared__ float sm[128 * ROWF];
    const float4* __restrict__ src = reinterpret_cast<const float4*>(pred) +
                        (size_t)blockIdx.x * (128 * ROWF / 4);
    float4* dst = reinterpret_cast<float4*>(sm);

    // ---- front-batched load: 2720 float4 by 256 threads, 11 per thread ----
    {
        float4 r[11];
        const int tid = threadIdx.x;
#pragma unroll
        for (int u = 0; u < 11; ++u) {
            int i = tid + u * 256;
            if (i < 128 * ROWF / 4) r[u] = src[i];
        }
#pragma unroll
        for (int u = 0; u < 11; ++u) {
            int i = tid + u * 256;
            if (i < 128 * ROWF / 4) dst[i] = r[u];
        }
    }
    __syncthreads();

    const int anchor = threadIdx.x >> 1;
    const int half   = threadIdx.x & 1;
    const float* a = sm + anchor * ROWF;
    const int base = 5 + half * 40;            // even: 5..44, odd: 45..84

    float m0 = a[base], m1 = a[base + 1];
#pragma unroll
    for (int k = 2; k < 40; k += 2) {
        m0 = fmaxf(m0, a[base + k]);
        m1 = fmaxf(m1, a[base + k + 1]);
    }
    float m = fmaxf(m0, m1);
    float other = __shfl_xor_sync(0xffffffffu, m, 1);

    if (half == 0) {
        float conf  = fmaxf(m, other);
        float score = __fmul_rn(a[4], conf);
        unsigned key = 0u;
        if (score >= CONF_T) key = __float_as_uint(score) | 0x80000000u;
        g_keys[blockIdx.x * 128 + anchor] = key;
    }
}

// ---------------------------------------------------------------------------
// Kernel B: per-batch select+sort+decode (32 blocks x 1024). Unchanged.
// ---------------------------------------------------------------------------
struct SelSmem {
    unsigned shi[NA];
    unsigned hist[4096];
    unsigned s8[512];
    unsigned sgsuf[33];
    unsigned long long cand[512];
    unsigned sh_bin, sh_acc, ncand;
    unsigned validw[10], inw[10];
};
#define SEL_SMEM_BYTES ((int)sizeof(SelSmem))

__global__ void __launch_bounds__(1024, 1) select_kernel(const float* __restrict__ pred,
                                                         const float* __restrict__ zone,
                                                         float* __restrict__ out)
{
    extern __shared__ char smem_raw[];
    SelSmem& S = *reinterpret_cast<SelSmem*>(smem_raw);

    const int b   = blockIdx.x;
    const int tid = threadIdx.x;

    if (tid == 0) { S.sh_bin = 0u; S.sh_acc = 0u; S.ncand = 0u; }
    if (tid < 10) { S.validw[tid] = 0u; S.inw[tid] = 0u; }
    for (int i = tid; i < 4096; i += 1024) S.hist[i] = 0u;
    __syncthreads();

    {
        const unsigned* __restrict__ keys = g_keys + (size_t)b * NA;
        for (int i = tid; i < NA; i += 1024) {
            unsigned hi = keys[i];
            S.shi[i] = hi;
            unsigned d = hi >> 20;
            unsigned am = __activemask();
            unsigned mm = __match_any_sync(am, d);
            if ((tid & 31) == (int)(__ffs(mm) - 1u))
                atomicAdd(&S.hist[d], (unsigned)__popc(mm));
        }
    }
    __syncthreads();

    unsigned thresh24 = 0u;

#pragma unroll
    for (int pass = 0; pass < 2; ++pass) {
        if (tid < 512) {
            unsigned s = 0;
#pragma unroll
            for (int k = 0; k < 8; ++k) s += S.hist[tid * 8 + k];
            S.s8[tid] = s;
        }
        __syncthreads();
        if (tid < 32) {
            unsigned s = 0;
#pragma unroll
            for (int k = 0; k < 16; ++k) s += S.s8[tid * 16 + k];
#pragma unroll
            for (int off = 1; off < 32; off <<= 1) {
                unsigned v = __shfl_down_sync(0xffffffffu, s, off);
                if (tid + off < 32) s += v;
            }
            S.sgsuf[tid] = s;
            if (tid == 0) S.sgsuf[32] = 0u;
        }
        __syncthreads();
        unsigned need = (unsigned)MD - S.sh_acc;
        if (tid < 512) {
            int g = tid >> 4;
            unsigned ws = 0;
            for (int j = tid + 1; j < (g + 1) * 16; ++j) ws += S.s8[j];
            unsigned above = S.sgsuf[g + 1] + ws;
            unsigned here  = above + S.s8[tid];
            if (here >= need && above < need) {
                unsigned cum = above; int sel = 0;
#pragma unroll
                for (int k = 7; k >= 0; --k) {
                    unsigned c = S.hist[tid * 8 + k];
                    if (cum + c >= need) { sel = k; break; }
                    cum += c;
                }
                S.sh_bin = (unsigned)(tid * 8 + sel);
                S.sh_acc += cum;
            }
        }
        __syncthreads();

        if (pass == 0) {
            unsigned p0 = S.sh_bin;
            __syncthreads();
            for (int i = tid; i < 4096; i += 1024) S.hist[i] = 0u;
            __syncthreads();
            for (int i = tid; i < NA; i += 1024) {
                unsigned hi = S.shi[i];
                if ((hi >> 20) == p0) {
                    unsigned d = (hi >> 8) & 0xFFFu;
                    unsigned am = __activemask();
                    unsigned mm = __match_any_sync(am, d);
                    if ((tid & 31) == (int)(__ffs(mm) - 1u))
                        atomicAdd(&S.hist[d], (unsigned)__popc(mm));
                }
            }
            __syncthreads();
            thresh24 = p0 << 12;
        } else {
            thresh24 |= S.sh_bin;
        }
    }

    for (int i = tid; i < NA; i += 1024) {
        unsigned hi = S.shi[i];
        if ((hi >> 8) >= thresh24) {
            unsigned p = atomicAdd(&S.ncand, 1u);
            if (p < 512u)
                S.cand[p] = ((unsigned long long)hi << 32) | (unsigned)(~(unsigned)i);
        }
    }
    __syncthreads();
    {
        unsigned nc = S.ncand; if (nc > 512u) nc = 512u;
        if (tid < 512 && (unsigned)tid >= nc) S.cand[tid] = 0ull;
    }
    __syncthreads();

    unsigned long long v = (tid < 512) ? S.cand[tid] : 0ull;
    for (int size = 2; size <= 512; size <<= 1) {
        for (int stride = size >> 1; stride > 0; stride >>= 1) {
            if (stride >= 32) {
                __syncthreads();
                if (tid < 512) S.cand[tid] = v;
                __syncthreads();
                if (tid < 512) {
                    unsigned long long vp = S.cand[tid ^ stride];
                    bool takeMax = ((tid & stride) == 0) == ((tid & size) == 0);
                    v = takeMax ? (v > vp ? v : vp) : (v < vp ? v : vp);
                }
            } else if (tid < 512) {
                unsigned long long vp = __shfl_xor_sync(0xffffffffu, v, stride);
                bool takeMax = ((tid & stride) == 0) == ((tid & size) == 0);
                v = takeMax ? (v > vp ? v : vp) : (v < vp ? v : vp);
            }
        }
    }

    if (tid < MD) {
        unsigned long long kk = v;
        unsigned aidx = ~((unsigned)kk);
        bool valid = (kk >> 32) != 0ull;
        if (!valid) aidx = 0;
        const float* a = pred + (size_t)(b * NA + aidx) * ROWF;

        float x = a[0], y = a[1], w = a[2], h = a[3], obj = a[4];

        float conf = a[5]; int cls = 0;
#pragma unroll 8
        for (int k = 1; k < 80; ++k) {
            float c = a[5 + k];
            if (c > conf) { conf = c; cls = k; }       // first-max == jnp.argmax
        }

        float hw = __fmul_rn(w, 0.5f), hh = __fmul_rn(h, 0.5f);
        float4 v0 = make_float4(__fadd_rn(x,-hw), __fadd_rn(y,-hh),
                                __fadd_rn(x, hw), __fadd_rn(y, hh));

        g_sbox[b*MD + tid]  = v0;
        g_sarea[b*MD + tid] = __fmul_rn(fmaxf(__fadd_rn(v0.z, -v0.x), 0.f),
                                        fmaxf(__fadd_rn(v0.w, -v0.y), 0.f));
        if (valid) atomicOr(&S.validw[tid >> 5], 1u << (tid & 31));

        float cx = __fmul_rn(__fadd_rn(v0.x, v0.z), 0.5f);
        float cy = __fmul_rn(__fadd_rn(v0.y, v0.w), 0.5f);

        int cnt = 0;
#pragma unroll
        for (int k2 = 0; k2 < 8; ++k2) {
            int km = (k2 + 7) & 7;
            float xi = zone[2*k2], yi = zone[2*k2+1];
            float xj = zone[2*km], yj = zone[2*km+1];
            bool gyi = yi > cy, gyj = yj > cy;
            if (gyi != gyj) {
                float gx = __fadd_rn(
                    __fdiv_rn(__fmul_rn(__fadd_rn(xj,-xi), __fadd_rn(cy,-yi)),
                              __fadd_rn(yj,-yi)), xi);
                if (gx > cx) cnt++;
            }
        }
        if (cnt & 1) atomicOr(&S.inw[tid >> 5], 1u << (tid & 31));

        size_t o = (size_t)b * MD + tid;
        out[OF_BOX + o*4 + 0] = v0.y;  out[OF_BOX + o*4 + 1] = v0.x;
        out[OF_BOX + o*4 + 2] = v0.w;  out[OF_BOX + o*4 + 3] = v0.z;
        out[OF_SC  + o]       = fmaxf(obj, conf);
        out[OF_CLS + o]       = (float)cls;
        out[OF_CTR + o*2]     = cy;    out[OF_CTR + o*2 + 1] = cx;
    }
    __syncthreads();
    if (tid < 10) {
        g_flags[b*20 + tid]      = S.validw[tid];
        g_flags[b*20 + 10 + tid] = S.inw[tid];
    }
}

// ---------------------------------------------------------------------------
// Kernel C: suppression bitmask on the full chip (320 blocks x 640).
// ---------------------------------------------------------------------------
__global__ void __launch_bounds__(640) mask_kernel()
{
    __shared__ float4 sbb[MD];
    __shared__ float  sA[MD];

    const int b  = blockIdx.x / 10;
    const int rg = blockIdx.x % 10;
    const int tid = threadIdx.x;

    if (tid < MD) { sbb[tid] = g_sbox[b*MD + tid]; sA[tid] = g_sarea[b*MD + tid]; }
    __syncthreads();

    int w = tid >> 5, l = tid & 31;
    int c    = w % 10;
    int half = w / 10;
    int i0   = rg * 30 + half * 15;
    int j    = c * 32 + l;
    int jmax = c * 32 + 31;
    bool jv  = (j < MD);
    float4 bj = jv ? sbb[j] : make_float4(0,0,0,0);
    float  ja = jv ? sA[j] : 0.f;

    for (int i = i0; i < i0 + 15; ++i) {
        unsigned bits = 0u;
        if (jmax > i) {
            float4 bi = sbb[i];
            float  ia = sA[i];
            bool sup = false;
            if (jv && j > i) {
                float ltx = fmaxf(bi.x, bj.x), lty = fmaxf(bi.y, bj.y);
                float rbx = fminf(bi.z, bj.z), rby = fminf(bi.w, bj.w);
                float iw  = fmaxf(__fadd_rn(rbx, -ltx), 0.f);
                float ih  = fmaxf(__fadd_rn(rby, -lty), 0.f);
                float inter = __fmul_rn(iw, ih);
                float denom = __fadd_rn(__fadd_rn(__fadd_rn(ia, ja), -inter), 1e-9f);
                sup = inter > __fmul_rn(NMS_T, denom);
            }
            bits = __ballot_sync(0xffffffffu, sup);
        }
        if (l == 0) g_mask[(b*MD + i)*10 + c] = bits;
    }
}

// ---------------------------------------------------------------------------
// Kernel D: branchless block-closure greedy scan (R8 version; best measured).
// ---------------------------------------------------------------------------
__global__ void __launch_bounds__(512, 1) fin_kernel(float* __restrict__ out)
{
    __shared__ unsigned smask[320*10];       // rows 300..319 zeroed
    __shared__ unsigned keepw[10];
    __shared__ unsigned flg[20];

    const int b   = blockIdx.x;
    const int tid = threadIdx.x;

    {   // vectorized mask load: 3000 words = 750 uint4
        const uint4* src = reinterpret_cast<const uint4*>(g_mask + b*MD*10);
        uint4* dst = reinterpret_cast<uint4*>(smask);
        for (int i = tid; i < 750; i += 512) dst[i] = src[i];
        for (int i = 3000 + tid; i < 3200; i += 512) smask[i] = 0u;
    }
    if (tid < 20) flg[tid] = g_flags[b*20 + tid];
    __syncthreads();

    if (tid < 32) {
        const int l  = tid;
        const int lw = (l < 10) ? l : 0;
        unsigned kw = (l < 10) ? flg[l] : 0u;

        for (int blk = 0; blk < 10; ++blk) {
            unsigned alive = __shfl_sync(0xffffffffu, kw, blk);
            const int base = blk * 32;

            unsigned r[32];
#pragma unroll
            for (int k = 0; k < 32; ++k)
                r[k] = smask[(base + k)*10 + blk];     // broadcast LDS

#pragma unroll
            for (int k = 0; k < 32; ++k)
                alive &= ~(r[k] & (unsigned)(((int)(alive << (31 - k))) >> 31));

            // branchless apply (lanes >= 10 compute garbage, discarded)
#pragma unroll
            for (int k = 0; k < 32; ++k) {
                unsigned am = (unsigned)(((int)(alive << (31 - k))) >> 31);
                kw &= ~(smask[(base + k)*10 + lw] & am);
            }
        }
        if (l < 10) keepw[l] = kw;
    }
    __syncthreads();

    if (tid < MD) {
        unsigned kp = (keepw[tid >> 5] >> (tid & 31)) & 1u;
        unsigned in = (flg[10 + (tid >> 5)] >> (tid & 31)) & 1u;
        size_t o = (size_t)b * MD + tid;
        out[OF_KEEP + o] = (float)kp;
        out[OF_INZ  + o] = (kp && in) ? 1.f : 0.f;
    }
}

extern "C" void kernel_launch(void* const* d_in, const int* in_sizes, int n_in,
                              void* d_out, int out_size)
{
    const float* pred = (const float*)d_in[0];
    const float* zone = (const float*)d_in[1];
    float* out = (float*)d_out;

    static int attr_done = 0;
    if (!attr_done) {
        cudaFuncSetAttribute(select_kernel,
                             cudaFuncAttributeMaxDynamicSharedMemorySize,
                             SEL_SMEM_BYTES);
        attr_done = 1;
    }

    score_kernel<<<TOTAL / 128, 256>>>(pred);
    select_kernel<<<NB, 1024, SEL_SMEM_BYTES>>>(pred, zone, out);
    mask_kernel<<<NB * 10, 640>>>();
    fin_kernel<<<NB, 512>>>(out);
}

// round 11
// speedup vs baseline: 1.1702x; 1.0322x over previous
#include <cuda_runtime.h>

#define NB   32
#define NA   8400
#define ROWF 85
#define MD   300
#define TOTAL (NB*NA)
#define CONF_T 0.2f
#define NMS_T  0.45f

// output layout: concatenated float32, reference return order
#define OF_BOX  0         // 32*300*4 = 38400
#define OF_INZ  38400     // 9600
#define OF_SC   48000     // 9600
#define OF_CLS  57600     // 9600
#define OF_CTR  67200     // 19200
#define OF_KEEP 86400     // 9600  -> total 96000

__device__ unsigned g_keys[TOTAL];     // ordered score bits (0 if below thresh)
__device__ float4   g_sbox[NB*MD];
__device__ float    g_sarea[NB*MD];
__device__ unsigned g_flags[NB*20];    // [0..9] valid, [10..19] inside
__device__ unsigned g_mask[NB*MD*10];  // row-major [b][row][chunk]

// ---------------------------------------------------------------------------
// Kernel A: per-anchor score -> 32-bit key.
// Load: 256 threads, 11 batched LDG.128 each (explicit MLP).
// Tail: 128 threads, one anchor each, stride-85 scalar LDS (conflict-free:
// 85 mod 32 = 21 is odd -> lane->bank bijection).
// ---------------------------------------------------------------------------
__global__ void __launch_bounds__(256) score_kernel(const float* __restrict__ pred)
{
    __shared__ float sm[128 * ROWF];
    const float4* __restrict__ src = reinterpret_cast<const float4*>(pred) +
                        (size_t)blockIdx.x * (128 * ROWF / 4);
    float4* dst = reinterpret_cast<float4*>(sm);

    {
        float4 r[11];
        const int tid = threadIdx.x;
#pragma unroll
        for (int u = 0; u < 11; ++u) {
            int i = tid + u * 256;
            if (i < 128 * ROWF / 4) r[u] = src[i];
        }
#pragma unroll
        for (int u = 0; u < 11; ++u) {
            int i = tid + u * 256;
            if (i < 128 * ROWF / 4) dst[i] = r[u];
        }
    }
    __syncthreads();

    if (threadIdx.x < 128) {
        const int t = threadIdx.x;
        const float* a = sm + t * ROWF;

        float obj = a[4];
        float m0 = a[5], m1 = a[6], m2 = a[7], m3 = a[8];
#pragma unroll
        for (int k = 9; k < 85; k += 4) {
            m0 = fmaxf(m0, a[k]);   m1 = fmaxf(m1, a[k+1]);
            m2 = fmaxf(m2, a[k+2]); m3 = fmaxf(m3, a[k+3]);
        }
        float conf  = fmaxf(fmaxf(m0, m1), fmaxf(m2, m3));
        float score = __fmul_rn(obj, conf);

        unsigned key = 0u;
        if (score >= CONF_T) key = __float_as_uint(score) | 0x80000000u;
        g_keys[blockIdx.x * 128 + t] = key;
    }
}

// ---------------------------------------------------------------------------
// Kernel B: per-batch select+sort+decode (32 blocks x 1024). Unchanged.
// ---------------------------------------------------------------------------
struct SelSmem {
    unsigned shi[NA];
    unsigned hist[4096];
    unsigned s8[512];
    unsigned sgsuf[33];
    unsigned long long cand[512];
    unsigned sh_bin, sh_acc, ncand;
    unsigned validw[10], inw[10];
};
#define SEL_SMEM_BYTES ((int)sizeof(SelSmem))

__global__ void __launch_bounds__(1024, 1) select_kernel(const float* __restrict__ pred,
                                                         const float* __restrict__ zone,
                                                         float* __restrict__ out)
{
    extern __shared__ char smem_raw[];
    SelSmem& S = *reinterpret_cast<SelSmem*>(smem_raw);

    const int b   = blockIdx.x;
    const int tid = threadIdx.x;

    if (tid == 0) { S.sh_bin = 0u; S.sh_acc = 0u; S.ncand = 0u; }
    if (tid < 10) { S.validw[tid] = 0u; S.inw[tid] = 0u; }
    for (int i = tid; i < 4096; i += 1024) S.hist[i] = 0u;
    __syncthreads();

    {
        const unsigned* __restrict__ keys = g_keys + (size_t)b * NA;
        for (int i = tid; i < NA; i += 1024) {
            unsigned hi = keys[i];
            S.shi[i] = hi;
            unsigned d = hi >> 20;
            unsigned am = __activemask();
            unsigned mm = __match_any_sync(am, d);
            if ((tid & 31) == (int)(__ffs(mm) - 1u))
                atomicAdd(&S.hist[d], (unsigned)__popc(mm));
        }
    }
    __syncthreads();

    unsigned thresh24 = 0u;

#pragma unroll
    for (int pass = 0; pass < 2; ++pass) {
        if (tid < 512) {
            unsigned s = 0;
#pragma unroll
            for (int k = 0; k < 8; ++k) s += S.hist[tid * 8 + k];
            S.s8[tid] = s;
        }
        __syncthreads();
        if (tid < 32) {
            unsigned s = 0;
#pragma unroll
            for (int k = 0; k < 16; ++k) s += S.s8[tid * 16 + k];
#pragma unroll
            for (int off = 1; off < 32; off <<= 1) {
                unsigned v = __shfl_down_sync(0xffffffffu, s, off);
                if (tid + off < 32) s += v;
            }
            S.sgsuf[tid] = s;
            if (tid == 0) S.sgsuf[32] = 0u;
        }
        __syncthreads();
        unsigned need = (unsigned)MD - S.sh_acc;
        if (tid < 512) {
            int g = tid >> 4;
            unsigned ws = 0;
            for (int j = tid + 1; j < (g + 1) * 16; ++j) ws += S.s8[j];
            unsigned above = S.sgsuf[g + 1] + ws;
            unsigned here  = above + S.s8[tid];
            if (here >= need && above < need) {
                unsigned cum = above; int sel = 0;
#pragma unroll
                for (int k = 7; k >= 0; --k) {
                    unsigned c = S.hist[tid * 8 + k];
                    if (cum + c >= need) { sel = k; break; }
                    cum += c;
                }
                S.sh_bin = (unsigned)(tid * 8 + sel);
                S.sh_acc += cum;
            }
        }
        __syncthreads();

        if (pass == 0) {
            unsigned p0 = S.sh_bin;
            __syncthreads();
            for (int i = tid; i < 4096; i += 1024) S.hist[i] = 0u;
            __syncthreads();
            for (int i = tid; i < NA; i += 1024) {
                unsigned hi = S.shi[i];
                if ((hi >> 20) == p0) {
                    unsigned d = (hi >> 8) & 0xFFFu;
                    unsigned am = __activemask();
                    unsigned mm = __match_any_sync(am, d);
                    if ((tid & 31) == (int)(__ffs(mm) - 1u))
                        atomicAdd(&S.hist[d], (unsigned)__popc(mm));
                }
            }
            __syncthreads();
            thresh24 = p0 << 12;
        } else {
            thresh24 |= S.sh_bin;
        }
    }

    for (int i = tid; i < NA; i += 1024) {
        unsigned hi = S.shi[i];
        if ((hi >> 8) >= thresh24) {
            unsigned p = atomicAdd(&S.ncand, 1u);
            if (p < 512u)
                S.cand[p] = ((unsigned long long)hi << 32) | (unsigned)(~(unsigned)i);
        }
    }
    __syncthreads();
    {
        unsigned nc = S.ncand; if (nc > 512u) nc = 512u;
        if (tid < 512 && (unsigned)tid >= nc) S.cand[tid] = 0ull;
    }
    __syncthreads();

    unsigned long long v = (tid < 512) ? S.cand[tid] : 0ull;
    for (int size = 2; size <= 512; size <<= 1) {
        for (int stride = size >> 1; stride > 0; stride >>= 1) {
            if (stride >= 32) {
                __syncthreads();
                if (tid < 512) S.cand[tid] = v;
                __syncthreads();
                if (tid < 512) {
                    unsigned long long vp = S.cand[tid ^ stride];
                    bool takeMax = ((tid & stride) == 0) == ((tid & size) == 0);
                    v = takeMax ? (v > vp ? v : vp) : (v < vp ? v : vp);
                }
            } else if (tid < 512) {
                unsigned long long vp = __shfl_xor_sync(0xffffffffu, v, stride);
                bool takeMax = ((tid & stride) == 0) == ((tid & size) == 0);
                v = takeMax ? (v > vp ? v : vp) : (v < vp ? v : vp);
            }
        }
    }

    if (tid < MD) {
        unsigned long long kk = v;
        unsigned aidx = ~((unsigned)kk);
        bool valid = (kk >> 32) != 0ull;
        if (!valid) aidx = 0;
        const float* a = pred + (size_t)(b * NA + aidx) * ROWF;

        float x = a[0], y = a[1], w = a[2], h = a[3], obj = a[4];

        float conf = a[5]; int cls = 0;
#pragma unroll 8
        for (int k = 1; k < 80; ++k) {
            float c = a[5 + k];
            if (c > conf) { conf = c; cls = k; }       // first-max == jnp.argmax
        }

        float hw = __fmul_rn(w, 0.5f), hh = __fmul_rn(h, 0.5f);
        float4 v0 = make_float4(__fadd_rn(x,-hw), __fadd_rn(y,-hh),
                                __fadd_rn(x, hw), __fadd_rn(y, hh));

        g_sbox[b*MD + tid]  = v0;
        g_sarea[b*MD + tid] = __fmul_rn(fmaxf(__fadd_rn(v0.z, -v0.x), 0.f),
                                        fmaxf(__fadd_rn(v0.w, -v0.y), 0.f));
        if (valid) atomicOr(&S.validw[tid >> 5], 1u << (tid & 31));

        float cx = __fmul_rn(__fadd_rn(v0.x, v0.z), 0.5f);
        float cy = __fmul_rn(__fadd_rn(v0.y, v0.w), 0.5f);

        int cnt = 0;
#pragma unroll
        for (int k2 = 0; k2 < 8; ++k2) {
            int km = (k2 + 7) & 7;
            float xi = zone[2*k2], yi = zone[2*k2+1];
            float xj = zone[2*km], yj = zone[2*km+1];
            bool gyi = yi > cy, gyj = yj > cy;
            if (gyi != gyj) {
                float gx = __fadd_rn(
                    __fdiv_rn(__fmul_rn(__fadd_rn(xj,-xi), __fadd_rn(cy,-yi)),
                              __fadd_rn(yj,-yi)), xi);
                if (gx > cx) cnt++;
            }
        }
        if (cnt & 1) atomicOr(&S.inw[tid >> 5], 1u << (tid & 31));

        size_t o = (size_t)b * MD + tid;
        out[OF_BOX + o*4 + 0] = v0.y;  out[OF_BOX + o*4 + 1] = v0.x;
        out[OF_BOX + o*4 + 2] = v0.w;  out[OF_BOX + o*4 + 3] = v0.z;
        out[OF_SC  + o]       = fmaxf(obj, conf);
        out[OF_CLS + o]       = (float)cls;
        out[OF_CTR + o*2]     = cy;    out[OF_CTR + o*2 + 1] = cx;
    }
    __syncthreads();
    if (tid < 10) {
        g_flags[b*20 + tid]      = S.validw[tid];
        g_flags[b*20 + 10 + tid] = S.inw[tid];
    }
}

// ---------------------------------------------------------------------------
// Kernel C: suppression bitmask on the full chip (320 blocks x 640).
// ---------------------------------------------------------------------------
__global__ void __launch_bounds__(640) mask_kernel()
{
    __shared__ float4 sbb[MD];
    __shared__ float  sA[MD];

    const int b  = blockIdx.x / 10;
    const int rg = blockIdx.x % 10;
    const int tid = threadIdx.x;

    if (tid < MD) { sbb[tid] = g_sbox[b*MD + tid]; sA[tid] = g_sarea[b*MD + tid]; }
    __syncthreads();

    int w = tid >> 5, l = tid & 31;
    int c    = w % 10;
    int half = w / 10;
    int i0   = rg * 30 + half * 15;
    int j    = c * 32 + l;
    int jmax = c * 32 + 31;
    bool jv  = (j < MD);
    float4 bj = jv ? sbb[j] : make_float4(0,0,0,0);
    float  ja = jv ? sA[j] : 0.f;

    for (int i = i0; i < i0 + 15; ++i) {
        unsigned bits = 0u;
        if (jmax > i) {
            float4 bi = sbb[i];
            float  ia = sA[i];
            bool sup = false;
            if (jv && j > i) {
                float ltx = fmaxf(bi.x, bj.x), lty = fmaxf(bi.y, bj.y);
                float rbx = fminf(bi.z, bj.z), rby = fminf(bi.w, bj.w);
                float iw  = fmaxf(__fadd_rn(rbx, -ltx), 0.f);
                float ih  = fmaxf(__fadd_rn(rby, -lty), 0.f);
                float inter = __fmul_rn(iw, ih);
                float denom = __fadd_rn(__fadd_rn(__fadd_rn(ia, ja), -inter), 1e-9f);
                sup = inter > __fmul_rn(NMS_T, denom);
            }
            bits = __ballot_sync(0xffffffffu, sup);
        }
        if (l == 0) g_mask[(b*MD + i)*10 + c] = bits;
    }
}

// ---------------------------------------------------------------------------
// Kernel D: block-closure greedy scan; closure blocked in groups of 8 so the
// diagonal words live in registers (no spill -> no LDL in the serial chain).
// ---------------------------------------------------------------------------
__global__ void __launch_bounds__(512, 1) fin_kernel(float* __restrict__ out)
{
    __shared__ unsigned smask[320*10];       // rows 300..319 zeroed
    __shared__ unsigned keepw[10];
    __shared__ unsigned flg[20];

    const int b   = blockIdx.x;
    const int tid = threadIdx.x;

    {   // vectorized mask load: 3000 words = 750 uint4
        const uint4* src = reinterpret_cast<const uint4*>(g_mask + b*MD*10);
        uint4* dst = reinterpret_cast<uint4*>(smask);
        for (int i = tid; i < 750; i += 512) dst[i] = src[i];
        for (int i = 3000 + tid; i < 3200; i += 512) smask[i] = 0u;
    }
    if (tid < 20) flg[tid] = g_flags[b*20 + tid];
    __syncthreads();

    if (tid < 32) {
        const int l  = tid;
        const int lw = (l < 10) ? l : 0;
        unsigned kw = (l < 10) ? flg[l] : 0u;

        for (int blk = 0; blk < 10; ++blk) {
            unsigned alive = __shfl_sync(0xffffffffu, kw, blk);
            const int base = blk * 32;

            // closure in groups of 8: r[8] stays in registers
#pragma unroll
            for (int g = 0; g < 4; ++g) {
                unsigned r[8];
#pragma unroll
                for (int k = 0; k < 8; ++k)
                    r[k] = smask[(base + g*8 + k)*10 + blk];   // broadcast LDS
#pragma unroll
                for (int k = 0; k < 8; ++k) {
                    int kk = g*8 + k;
                    alive &= ~(r[k] & (unsigned)(((int)(alive << (31 - kk))) >> 31));
                }
            }

            // branchless apply (lanes >= 10 compute garbage, discarded)
#pragma unroll 8
            for (int k = 0; k < 32; ++k) {
                unsigned am = (unsigned)(((int)(alive << (31 - k))) >> 31);
                kw &= ~(smask[(base + k)*10 + lw] & am);
            }
        }
        if (l < 10) keepw[l] = kw;
    }
    __syncthreads();

    if (tid < MD) {
        unsigned kp = (keepw[tid >> 5] >> (tid & 31)) & 1u;
        unsigned in = (flg[10 + (tid >> 5)] >> (tid & 31)) & 1u;
        size_t o = (size_t)b * MD + tid;
        out[OF_KEEP + o] = (float)kp;
        out[OF_INZ  + o] = (kp && in) ? 1.f : 0.f;
    }
}

extern "C" void kernel_launch(void* const* d_in, const int* in_sizes, int n_in,
                              void* d_out, int out_size)
{
    const float* pred = (const float*)d_in[0];
    const float* zone = (const float*)d_in[1];
    float* out = (float*)d_out;

    static int attr_done = 0;
    if (!attr_done) {
        cudaFuncSetAttribute(select_kernel,
                             cudaFuncAttributeMaxDynamicSharedMemorySize,
                             SEL_SMEM_BYTES);
        attr_done = 1;
    }

    score_kernel<<<TOTAL / 128, 256>>>(pred);
    select_kernel<<<NB, 1024, SEL_SMEM_BYTES>>>(pred, zone, out);
    mask_kernel<<<NB * 10, 640>>>();
    fin_kernel<<<NB, 512>>>(out);
}

// round 12
// speedup vs baseline: 1.3277x; 1.1346x over previous
#include <cuda_runtime.h>
#include <cstdint>

#define NB   32
#define NA   8400
#define ROWF 85
#define MD   300
#define TOTAL (NB*NA)
#define CONF_T 0.2f
#define NMS_T  0.45f
#define TILE_BYTES (128*ROWF*4)   // 43520, multiple of 16

// output layout: concatenated float32, reference return order
#define OF_BOX  0         // 32*300*4 = 38400
#define OF_INZ  38400     // 9600
#define OF_SC   48000     // 9600
#define OF_CLS  57600     // 9600
#define OF_CTR  67200     // 19200
#define OF_KEEP 86400     // 9600  -> total 96000

__device__ unsigned g_keys[TOTAL];     // ordered score bits (0 if below thresh)
__device__ float4   g_sbox[NB*MD];
__device__ float    g_sarea[NB*MD];
__device__ unsigned g_flags[NB*20];    // [0..9] valid, [10..19] inside
__device__ unsigned g_mask[NB*MD*10];  // row-major [b][row][chunk]

__device__ __forceinline__ uint32_t smem_u32(const void* p) {
    uint32_t a;
    asm("{ .reg .u64 t; cvta.to.shared.u64 t, %1; cvt.u32.u64 %0, t; }"
        : "=r"(a) : "l"(p));
    return a;
}

// ---------------------------------------------------------------------------
// Kernel A: per-anchor score -> 32-bit key.
// Tile loaded by ONE cp.async.bulk (TMA): full 43.5 KB in flight per block,
// no warp-issued LDGs. Tail: 128 threads, stride-85 LDS (conflict-free).
// ---------------------------------------------------------------------------
__global__ void __launch_bounds__(256) score_kernel(const float* __restrict__ pred)
{
    __shared__ __align__(16) float sm[128 * ROWF];
    __shared__ __align__(8)  unsigned long long mbar;

    const int tid = threadIdx.x;
    const uint32_t mb  = smem_u32(&mbar);
    const uint32_t dst = smem_u32(sm);
    const char* src = (const char*)pred + (size_t)blockIdx.x * TILE_BYTES;

    if (tid == 0)
        asm volatile("mbarrier.init.shared.b64 [%0], 1;" :: "r"(mb) : "memory");
    __syncthreads();
    if (tid == 0) {
        asm volatile("mbarrier.arrive.expect_tx.shared.b64 _, [%0], %1;"
                     :: "r"(mb), "r"((unsigned)TILE_BYTES) : "memory");
        asm volatile("cp.async.bulk.shared::cta.global.mbarrier::complete_tx::bytes"
                     " [%0], [%1], %2, [%3];"
                     :: "r"(dst), "l"(src), "r"((unsigned)TILE_BYTES), "r"(mb)
                     : "memory");
    }
    {   // wait parity 0 (barrier re-initialized every launch)
        asm volatile(
            "{\n\t"
            ".reg .pred P;\n\t"
            "WL_%=:\n\t"
            "mbarrier.try_wait.parity.acquire.cta.shared::cta.b64 P, [%0], 0, 0x989680;\n\t"
            "@P bra.uni WD_%=;\n\t"
            "bra.uni WL_%=;\n\t"
            "WD_%=:\n\t"
            "}" :: "r"(mb) : "memory");
    }

    if (tid < 128) {
        const float* a = sm + tid * ROWF;     // stride 85: conflict-free

        float obj = a[4];
        float m0 = a[5], m1 = a[6], m2 = a[7], m3 = a[8];
#pragma unroll
        for (int k = 9; k < 85; k += 4) {
            m0 = fmaxf(m0, a[k]);   m1 = fmaxf(m1, a[k+1]);
            m2 = fmaxf(m2, a[k+2]); m3 = fmaxf(m3, a[k+3]);
        }
        float conf  = fmaxf(fmaxf(m0, m1), fmaxf(m2, m3));
        float score = __fmul_rn(obj, conf);

        unsigned key = 0u;
        if (score >= CONF_T) key = __float_as_uint(score) | 0x80000000u;
        g_keys[blockIdx.x * 128 + tid] = key;
    }
}

// ---------------------------------------------------------------------------
// Kernel B: per-batch select+sort+decode (32 blocks x 1024). Unchanged.
// ---------------------------------------------------------------------------
struct SelSmem {
    unsigned shi[NA];
    unsigned hist[4096];
    unsigned s8[512];
    unsigned sgsuf[33];
    unsigned long long cand[512];
    unsigned sh_bin, sh_acc, ncand;
    unsigned validw[10], inw[10];
};
#define SEL_SMEM_BYTES ((int)sizeof(SelSmem))

__global__ void __launch_bounds__(1024, 1) select_kernel(const float* __restrict__ pred,
                                                         const float* __restrict__ zone,
                                                         float* __restrict__ out)
{
    extern __shared__ char smem_raw[];
    SelSmem& S = *reinterpret_cast<SelSmem*>(smem_raw);

    const int b   = blockIdx.x;
    const int tid = threadIdx.x;

    if (tid == 0) { S.sh_bin = 0u; S.sh_acc = 0u; S.ncand = 0u; }
    if (tid < 10) { S.validw[tid] = 0u; S.inw[tid] = 0u; }
    for (int i = tid; i < 4096; i += 1024) S.hist[i] = 0u;
    __syncthreads();

    {
        const unsigned* __restrict__ keys = g_keys + (size_t)b * NA;
        for (int i = tid; i < NA; i += 1024) {
            unsigned hi = keys[i];
            S.shi[i] = hi;
            unsigned d = hi >> 20;
            unsigned am = __activemask();
            unsigned mm = __match_any_sync(am, d);
            if ((tid & 31) == (int)(__ffs(mm) - 1u))
                atomicAdd(&S.hist[d], (unsigned)__popc(mm));
        }
    }
    __syncthreads();

    unsigned thresh24 = 0u;

#pragma unroll
    for (int pass = 0; pass < 2; ++pass) {
        if (tid < 512) {
            unsigned s = 0;
#pragma unroll
            for (int k = 0; k < 8; ++k) s += S.hist[tid * 8 + k];
            S.s8[tid] = s;
        }
        __syncthreads();
        if (tid < 32) {
            unsigned s = 0;
#pragma unroll
            for (int k = 0; k < 16; ++k) s += S.s8[tid * 16 + k];
#pragma unroll
            for (int off = 1; off < 32; off <<= 1) {
                unsigned v = __shfl_down_sync(0xffffffffu, s, off);
                if (tid + off < 32) s += v;
            }
            S.sgsuf[tid] = s;
            if (tid == 0) S.sgsuf[32] = 0u;
        }
        __syncthreads();
        unsigned need = (unsigned)MD - S.sh_acc;
        if (tid < 512) {
            int g = tid >> 4;
            unsigned ws = 0;
            for (int j = tid + 1; j < (g + 1) * 16; ++j) ws += S.s8[j];
            unsigned above = S.sgsuf[g + 1] + ws;
            unsigned here  = above + S.s8[tid];
            if (here >= need && above < need) {
                unsigned cum = above; int sel = 0;
#pragma unroll
                for (int k = 7; k >= 0; --k) {
                    unsigned c = S.hist[tid * 8 + k];
                    if (cum + c >= need) { sel = k; break; }
                    cum += c;
                }
                S.sh_bin = (unsigned)(tid * 8 + sel);
                S.sh_acc += cum;
            }
        }
        __syncthreads();

        if (pass == 0) {
            unsigned p0 = S.sh_bin;
            __syncthreads();
            for (int i = tid; i < 4096; i += 1024) S.hist[i] = 0u;
            __syncthreads();
            for (int i = tid; i < NA; i += 1024) {
                unsigned hi = S.shi[i];
                if ((hi >> 20) == p0) {
                    unsigned d = (hi >> 8) & 0xFFFu;
                    unsigned am = __activemask();
                    unsigned mm = __match_any_sync(am, d);
                    if ((tid & 31) == (int)(__ffs(mm) - 1u))
                        atomicAdd(&S.hist[d], (unsigned)__popc(mm));
                }
            }
            __syncthreads();
            thresh24 = p0 << 12;
        } else {
            thresh24 |= S.sh_bin;
        }
    }

    for (int i = tid; i < NA; i += 1024) {
        unsigned hi = S.shi[i];
        if ((hi >> 8) >= thresh24) {
            unsigned p = atomicAdd(&S.ncand, 1u);
            if (p < 512u)
                S.cand[p] = ((unsigned long long)hi << 32) | (unsigned)(~(unsigned)i);
        }
    }
    __syncthreads();
    {
        unsigned nc = S.ncand; if (nc > 512u) nc = 512u;
        if (tid < 512 && (unsigned)tid >= nc) S.cand[tid] = 0ull;
    }
    __syncthreads();

    unsigned long long v = (tid < 512) ? S.cand[tid] : 0ull;
    for (int size = 2; size <= 512; size <<= 1) {
        for (int stride = size >> 1; stride > 0; stride >>= 1) {
            if (stride >= 32) {
                __syncthreads();
                if (tid < 512) S.cand[tid] = v;
                __syncthreads();
                if (tid < 512) {
                    unsigned long long vp = S.cand[tid ^ stride];
                    bool takeMax = ((tid & stride) == 0) == ((tid & size) == 0);
                    v = takeMax ? (v > vp ? v : vp) : (v < vp ? v : vp);
                }
            } else if (tid < 512) {
                unsigned long long vp = __shfl_xor_sync(0xffffffffu, v, stride);
                bool takeMax = ((tid & stride) == 0) == ((tid & size) == 0);
                v = takeMax ? (v > vp ? v : vp) : (v < vp ? v : vp);
            }
        }
    }

    if (tid < MD) {
        unsigned long long kk = v;
        unsigned aidx = ~((unsigned)kk);
        bool valid = (kk >> 32) != 0ull;
        if (!valid) aidx = 0;
        const float* a = pred + (size_t)(b * NA + aidx) * ROWF;

        float x = a[0], y = a[1], w = a[2], h = a[3], obj = a[4];

        float conf = a[5]; int cls = 0;
#pragma unroll 8
        for (int k = 1; k < 80; ++k) {
            float c = a[5 + k];
            if (c > conf) { conf = c; cls = k; }       // first-max == jnp.argmax
        }

        float hw = __fmul_rn(w, 0.5f), hh = __fmul_rn(h, 0.5f);
        float4 v0 = make_float4(__fadd_rn(x,-hw), __fadd_rn(y,-hh),
                                __fadd_rn(x, hw), __fadd_rn(y, hh));

        g_sbox[b*MD + tid]  = v0;
        g_sarea[b*MD + tid] = __fmul_rn(fmaxf(__fadd_rn(v0.z, -v0.x), 0.f),
                                        fmaxf(__fadd_rn(v0.w, -v0.y), 0.f));
        if (valid) atomicOr(&S.validw[tid >> 5], 1u << (tid & 31));

        float cx = __fmul_rn(__fadd_rn(v0.x, v0.z), 0.5f);
        float cy = __fmul_rn(__fadd_rn(v0.y, v0.w), 0.5f);

        int cnt = 0;
#pragma unroll
        for (int k2 = 0; k2 < 8; ++k2) {
            int km = (k2 + 7) & 7;
            float xi = zone[2*k2], yi = zone[2*k2+1];
            float xj = zone[2*km], yj = zone[2*km+1];
            bool gyi = yi > cy, gyj = yj > cy;
            if (gyi != gyj) {
                float gx = __fadd_rn(
                    __fdiv_rn(__fmul_rn(__fadd_rn(xj,-xi), __fadd_rn(cy,-yi)),
                              __fadd_rn(yj,-yi)), xi);
                if (gx > cx) cnt++;
            }
        }
        if (cnt & 1) atomicOr(&S.inw[tid >> 5], 1u << (tid & 31));

        size_t o = (size_t)b * MD + tid;
        out[OF_BOX + o*4 + 0] = v0.y;  out[OF_BOX + o*4 + 1] = v0.x;
        out[OF_BOX + o*4 + 2] = v0.w;  out[OF_BOX + o*4 + 3] = v0.z;
        out[OF_SC  + o]       = fmaxf(obj, conf);
        out[OF_CLS + o]       = (float)cls;
        out[OF_CTR + o*2]     = cy;    out[OF_CTR + o*2 + 1] = cx;
    }
    __syncthreads();
    if (tid < 10) {
        g_flags[b*20 + tid]      = S.validw[tid];
        g_flags[b*20 + 10 + tid] = S.inw[tid];
    }
}

// ---------------------------------------------------------------------------
// Kernel C: suppression bitmask on the full chip (320 blocks x 640).
// ---------------------------------------------------------------------------
__global__ void __launch_bounds__(640) mask_kernel()
{
    __shared__ float4 sbb[MD];
    __shared__ float  sA[MD];

    const int b  = blockIdx.x / 10;
    const int rg = blockIdx.x % 10;
    const int tid = threadIdx.x;

    if (tid < MD) { sbb[tid] = g_sbox[b*MD + tid]; sA[tid] = g_sarea[b*MD + tid]; }
    __syncthreads();

    int w = tid >> 5, l = tid & 31;
    int c    = w % 10;
    int half = w / 10;
    int i0   = rg * 30 + half * 15;
    int j    = c * 32 + l;
    int jmax = c * 32 + 31;
    bool jv  = (j < MD);
    float4 bj = jv ? sbb[j] : make_float4(0,0,0,0);
    float  ja = jv ? sA[j] : 0.f;

    for (int i = i0; i < i0 + 15; ++i) {
        unsigned bits = 0u;
        if (jmax > i) {
            float4 bi = sbb[i];
            float  ia = sA[i];
            bool sup = false;
            if (jv && j > i) {
                float ltx = fmaxf(bi.x, bj.x), lty = fmaxf(bi.y, bj.y);
                float rbx = fminf(bi.z, bj.z), rby = fminf(bi.w, bj.w);
                float iw  = fmaxf(__fadd_rn(rbx, -ltx), 0.f);
                float ih  = fmaxf(__fadd_rn(rby, -lty), 0.f);
                float inter = __fmul_rn(iw, ih);
                float denom = __fadd_rn(__fadd_rn(__fadd_rn(ia, ja), -inter), 1e-9f);
                sup = inter > __fmul_rn(NMS_T, denom);
            }
            bits = __ballot_sync(0xffffffffu, sup);
        }
        if (l == 0) g_mask[(b*MD + i)*10 + c] = bits;
    }
}

// ---------------------------------------------------------------------------
// Kernel D: branchless block-closure greedy scan (R8 version; best measured).
// ---------------------------------------------------------------------------
__global__ void __launch_bounds__(512, 1) fin_kernel(float* __restrict__ out)
{
    __shared__ unsigned smask[320*10];       // rows 300..319 zeroed
    __shared__ unsigned keepw[10];
    __shared__ unsigned flg[20];

    const int b   = blockIdx.x;
    const int tid = threadIdx.x;

    {   // vectorized mask load: 3000 words = 750 uint4
        const uint4* src = reinterpret_cast<const uint4*>(g_mask + b*MD*10);
        uint4* dst = reinterpret_cast<uint4*>(smask);
        for (int i = tid; i < 750; i += 512) dst[i] = src[i];
        for (int i = 3000 + tid; i < 3200; i += 512) smask[i] = 0u;
    }
    if (tid < 20) flg[tid] = g_flags[b*20 + tid];
    __syncthreads();

    if (tid < 32) {
        const int l  = tid;
        const int lw = (l < 10) ? l : 0;
        unsigned kw = (l < 10) ? flg[l] : 0u;

        for (int blk = 0; blk < 10; ++blk) {
            unsigned alive = __shfl_sync(0xffffffffu, kw, blk);
            const int base = blk * 32;

            unsigned r[32];
#pragma unroll
            for (int k = 0; k < 32; ++k)
                r[k] = smask[(base + k)*10 + blk];     // broadcast LDS

#pragma unroll
            for (int k = 0; k < 32; ++k)
                alive &= ~(r[k] & (unsigned)(((int)(alive << (31 - k))) >> 31));

            // branchless apply (lanes >= 10 compute garbage, discarded)
#pragma unroll
            for (int k = 0; k < 32; ++k) {
                unsigned am = (unsigned)(((int)(alive << (31 - k))) >> 31);
                kw &= ~(smask[(base + k)*10 + lw] & am);
            }
        }
        if (l < 10) keepw[l] = kw;
    }
    __syncthreads();

    if (tid < MD) {
        unsigned kp = (keepw[tid >> 5] >> (tid & 31)) & 1u;
        unsigned in = (flg[10 + (tid >> 5)] >> (tid & 31)) & 1u;
        size_t o = (size_t)b * MD + tid;
        out[OF_KEEP + o] = (float)kp;
        out[OF_INZ  + o] = (kp && in) ? 1.f : 0.f;
    }
}

extern "C" void kernel_launch(void* const* d_in, const int* in_sizes, int n_in,
                              void* d_out, int out_size)
{
    const float* pred = (const float*)d_in[0];
    const float* zone = (const float*)d_in[1];
    float* out = (float*)d_out;

    static int attr_done = 0;
    if (!attr_done) {
        cudaFuncSetAttribute(select_kernel,
                             cudaFuncAttributeMaxDynamicSharedMemorySize,
                             SEL_SMEM_BYTES);
        attr_done = 1;
    }

    score_kernel<<<TOTAL / 128, 256>>>(pred);
    select_kernel<<<NB, 1024, SEL_SMEM_BYTES>>>(pred, zone, out);
    mask_kernel<<<NB * 10, 640>>>();
    fin_kernel<<<NB, 512>>>(out);
}